// round 12
// baseline (speedup 1.0000x reference)
#include <cuda_runtime.h>
#include <cuda_bf16.h>

#define EPS   1e-6f
#define NCOLS 4096
#define MAXB  8192
#define NBLK  444          // 148 SMs x 2 resident CTAs... persistent grid (see launch)

// Per-row streaks, per-CTA bce partials, completion counter (graph-replay safe).
__device__ int   g_ps[MAXB];       // max streak per row
__device__ float g_pw[NBLK];       // per-CTA sum of depth_weights * bce
__device__ unsigned int g_count = 0;

// Combine left (ap,as,ab | len la) with right (bp,bs,bb | len lb); result in a*.
#define SEG_COMBINE(ap, as, ab, la, bp, bs, bb, lb)              \
    do {                                                         \
        int _np = ((ap) == (la)) ? (la) + (bp) : (ap);           \
        int _ns = ((bs) == (lb)) ? (lb) + (as) : (bs);           \
        int _nb = max(max((ab), (bb)), (as) + (bp));             \
        (ap) = _np; (as) = _ns; (ab) = _nb;                      \
    } while (0)

// Leaf (8 contiguous elems) + 5-level warp tree -> 256-elem segment in lane 0.
__device__ __forceinline__ void leaf_and_tree(const float4& A, const float4& B_,
                                              const float4& TA, const float4& TB,
                                              const float4& WA, const float4& WB,
                                              float& wacc,
                                              int& pref, int& suf, int& best)
{
    float pp[8] = {A.x, A.y, A.z, A.w, B_.x, B_.y, B_.z, B_.w};
    float tt[8] = {TA.x, TA.y, TA.z, TA.w, TB.x, TB.y, TB.z, TB.w};
    float ww[8] = {WA.x, WA.y, WA.z, WA.w, WB.x, WB.y, WB.z, WB.w};

    int cur = 0, all = 1;
    pref = 0; best = 0;
#pragma unroll
    for (int e = 0; e < 8; e++) {
        bool tb = (tt[e] > 0.5f);
        bool pb = (pp[e] > 0.5f);
        int corr = (tb == pb) ? 1 : 0;
        float v = tb ? (pp[e] + EPS) : ((1.0f - pp[e]) + EPS);
        wacc = fmaf(ww[e], -__logf(v), wacc);
        cur  = corr ? (cur + 1) : 0;
        best = max(best, cur);
        all &= corr;
        pref += all;
    }
    suf = cur;

#pragma unroll
    for (int s = 0; s < 5; s++) {
        int len = 8 << s;
        int op = __shfl_down_sync(0xffffffffu, pref, 1 << s);
        int os = __shfl_down_sync(0xffffffffu, suf,  1 << s);
        int ob = __shfl_down_sync(0xffffffffu, best, 1 << s);
        SEG_COMBINE(pref, suf, best, len, op, os, ob, len);
    }
}

// Persistent CTAs: 512 threads (16 warps). TWO ADJACENT rows per iteration
// (contiguous 32KB region per array per CTA-iteration); all 12 LDG.128 are
// explicitly front-batched before either tree, so row 1's loads cover row 0's
// tree/barrier window. One __syncthreads per 2 rows. 64-reg budget (occ 2).
__global__ __launch_bounds__(512, 2)
void depth_loss_fused_kernel(const float4* __restrict__ p4,
                             const float4* __restrict__ t4,
                             const float4* __restrict__ w4,
                             float* __restrict__ out, int B)
{
    const int tid  = threadIdx.x;
    const int warp = tid >> 5;
    const int lane = tid & 31;
    const int N4   = NCOLS / 4;

    __shared__ int shp[2][2][16], shs[2][2][16], shb[2][2][16]; // [parity][slot][warp]
    __shared__ int s_isLast;

    float wacc = 0.0f;            // per-thread bce partial across all its rows
    int par = 0;

    for (int row = 2 * blockIdx.x; row < B; row += 2 * NBLK, par ^= 1) {
        const size_t b0 = (size_t)row * N4 + warp * 64 + lane * 2;
        const size_t b1 = b0 + N4;     // adjacent row

        // front-batch ALL 12 LDG.128 (both rows)
        float4 pA0 = __ldcs(&p4[b0]), pB0 = __ldcs(&p4[b0 + 1]);
        float4 tA0 = __ldcs(&t4[b0]), tB0 = __ldcs(&t4[b0 + 1]);
        float4 wA0 = __ldcs(&w4[b0]), wB0 = __ldcs(&w4[b0 + 1]);
        float4 pA1 = __ldcs(&p4[b1]), pB1 = __ldcs(&p4[b1 + 1]);
        float4 tA1 = __ldcs(&t4[b1]), tB1 = __ldcs(&t4[b1 + 1]);
        float4 wA1 = __ldcs(&w4[b1]), wB1 = __ldcs(&w4[b1 + 1]);

        int pref, suf, best;
        leaf_and_tree(pA0, pB0, tA0, tB0, wA0, wB0, wacc, pref, suf, best);
        if (lane == 0) { shp[par][0][warp] = pref; shs[par][0][warp] = suf; shb[par][0][warp] = best; }

        leaf_and_tree(pA1, pB1, tA1, tB1, wA1, wB1, wacc, pref, suf, best);
        if (lane == 0) { shp[par][1][warp] = pref; shs[par][1][warp] = suf; shb[par][1][warp] = best; }

        __syncthreads();

        // tid0 combines both rows while other warps start the next iteration
        // (parity slot [par] is not rewritten until iteration+2, fenced by
        // iteration+1's barrier).
        if (tid == 0) {
            int ap = shp[par][0][0], as = shs[par][0][0], ab = shb[par][0][0];
#pragma unroll
            for (int wi = 1; wi < 16; wi++)
                SEG_COMBINE(ap, as, ab, 256 * wi,
                            shp[par][0][wi], shs[par][0][wi], shb[par][0][wi], 256);
            g_ps[row] = ab;

            ap = shp[par][1][0]; as = shs[par][1][0]; ab = shb[par][1][0];
#pragma unroll
            for (int wi = 1; wi < 16; wi++)
                SEG_COMBINE(ap, as, ab, 256 * wi,
                            shp[par][1][wi], shs[par][1][wi], shb[par][1][wi], 256);
            g_ps[row + 1] = ab;
        }
    }

    // ---- CTA end: reduce per-thread bce partials, one fence+atomic per CTA ----
#pragma unroll
    for (int s = 16; s > 0; s >>= 1)
        wacc += __shfl_down_sync(0xffffffffu, wacc, s);
    __shared__ float shwf[16];
    if (lane == 0) shwf[warp] = wacc;
    __syncthreads();
    if (tid == 0) {
        float ws = shwf[0];
#pragma unroll
        for (int wi = 1; wi < 16; wi++) ws += shwf[wi];
        g_pw[blockIdx.x] = ws;
        __threadfence();                         // release partials + streaks
        unsigned int done = atomicAdd(&g_count, 1u);
        s_isLast = (done == (unsigned int)(gridDim.x - 1)) ? 1 : 0;
    }
    __syncthreads();

    // ---- last CTA: final deterministic reduction ----
    if (s_isLast) {
        __threadfence();   // acquire: see all CTAs' partials
        double dw = 0.0;
        long long dsi = 0;
        for (int i = tid; i < (int)gridDim.x; i += 512)
            dw += (double)g_pw[i];
        for (int r = tid; r < B; r += 2048) {
            int b0 = g_ps[r], b1 = g_ps[r + 512], b2 = g_ps[r + 1024], b3 = g_ps[r + 1536];
            dsi += (long long)b0 + b1 + b2 + b3;
        }
        __shared__ double    rdw[512];
        __shared__ long long rds[512];
        rdw[tid] = dw;
        rds[tid] = dsi;
        __syncthreads();
#pragma unroll
        for (int st = 256; st > 0; st >>= 1) {
            if (tid < st) { rdw[tid] += rdw[tid + st]; rds[tid] += rds[tid + st]; }
            __syncthreads();
        }
        if (tid == 0) {
            double BN   = (double)B * (double)NCOLS;
            double wbce = rdw[0] / BN;                       // mean(w * bce)
            double cwl  = 1.0 - ((double)rds[0]) / BN;       // mean(1 - streak/N)
            out[0] = (float)(0.5 * wbce + 0.5 * cwl);
            g_count = 0;                                     // reset for next replay
        }
    }
}

extern "C" void kernel_launch(void* const* d_in, const int* in_sizes, int n_in,
                              void* d_out, int out_size)
{
    const float4* p4 = (const float4*)d_in[0];   // y_pred
    const float4* t4 = (const float4*)d_in[1];   // y_true
    const float4* w4 = (const float4*)d_in[2];   // depth_weights
    int total = in_sizes[0];
    int B = total / NCOLS;                       // 8192

    depth_loss_fused_kernel<<<NBLK, 512>>>(p4, t4, w4, (float*)d_out, B);
}

// round 17
// speedup vs baseline: 1.1213x; 1.1213x over previous
#include <cuda_runtime.h>
#include <cuda_bf16.h>

#define EPS   1e-6f
#define NCOLS 4096
#define MAXB  8192
#define NBLK  444          // 148 SMs x 3 resident CTAs (persistent grid)
#define NS    4            // pipeline depth (smem seg slots)

// Per-row streaks, per-CTA bce partials, completion counter (graph-replay safe).
__device__ int   g_ps[MAXB];       // max streak per row
__device__ float g_pw[NBLK];       // per-CTA sum of depth_weights * bce
__device__ unsigned int g_count = 0;

// Combine left (ap,as,ab | len la) with right (bp,bs,bb | len lb); result in a*.
#define SEG_COMBINE(ap, as, ab, la, bp, bs, bb, lb)              \
    do {                                                         \
        int _np = ((ap) == (la)) ? (la) + (bp) : (ap);           \
        int _ns = ((bs) == (lb)) ? (lb) + (as) : (bs);           \
        int _nb = max(max((ab), (bb)), (as) + (bp));             \
        (ap) = _np; (as) = _ns; (ab) = _nb;                      \
    } while (0)

__device__ __forceinline__ unsigned smem_u32(const void* p) {
    unsigned a;
    asm("{ .reg .u64 t; cvta.to.shared.u64 t, %1; cvt.u32.u64 %0, t; }"
        : "=r"(a) : "l"(p));
    return a;
}
__device__ __forceinline__ void mbar_init(unsigned a, unsigned cnt) {
    asm volatile("mbarrier.init.shared.b64 [%0], %1;" :: "r"(a), "r"(cnt) : "memory");
}
__device__ __forceinline__ void mbar_arrive(unsigned a) {
    asm volatile("mbarrier.arrive.shared.b64 _, [%0];" :: "r"(a) : "memory");
}
__device__ __forceinline__ void mbar_wait(unsigned a, unsigned parity) {
    asm volatile(
        "{\n\t"
        ".reg .pred P;\n\t"
        "W%=:\n\t"
        "mbarrier.try_wait.parity.shared.b64 P, [%0], %1;\n\t"
        "@!P bra W%=;\n\t"
        "}"
        :: "r"(a), "r"(parity) : "memory");
}

// Persistent CTAs: 512 threads (16 warps), one row per iteration, lane i of
// warp w holding row elements [w*256 + i*8, +8). Instead of a per-row
// __syncthreads rendezvous, a depth-4 mbarrier pipeline bounds inter-warp
// drift to 4 rows: every warp arrives on full[s] after writing its segment
// (no wait); the rotating consumer warp (warp == s) waits full[s], combines,
// stores the row streak, and arrives free[s]; producers wait only on free[s]
// (the consumer's progress 4 rows back), never on each other.
__global__ __launch_bounds__(512, 3)
void depth_loss_fused_kernel(const float4* __restrict__ p4,
                             const float4* __restrict__ t4,
                             const float4* __restrict__ w4,
                             float* __restrict__ out, int B)
{
    const int tid  = threadIdx.x;
    const int warp = tid >> 5;
    const int lane = tid & 31;

    __shared__ int shp[NS][16], shs[NS][16], shb[NS][16];
    __shared__ alignas(8) unsigned long long mb_full[NS], mb_free[NS];
    __shared__ int s_isLast;

    const unsigned fullb = smem_u32(mb_full);
    const unsigned freeb = smem_u32(mb_free);

    if (tid == 0) {
#pragma unroll
        for (int s = 0; s < NS; s++) {
            mbar_init(fullb + 8u * s, 16);   // 16 warp arrivals per row
            mbar_init(freeb + 8u * s, 1);    // 1 consumer arrival per reuse
        }
    }
    __syncthreads();

    float wacc = 0.0f;            // per-thread bce partial across all its rows
    int k = 0;

    for (int row = blockIdx.x; row < B; row += NBLK, k++) {
        const int s = k & (NS - 1);
        const int c = k >> 2;                    // cycle through the slot ring
        const bool consumer = (warp == s);

        // producers: wait until slot s was consumed in the previous cycle
        if (!consumer && k >= NS)
            mbar_wait(freeb + 8u * s, (unsigned)((c - 1) & 1));

        const size_t base = (size_t)row * (NCOLS / 4) + warp * 64 + lane * 2;

        // front-batch all 6 LDG.128
        float4 pA = __ldcs(&p4[base]), pB = __ldcs(&p4[base + 1]);
        float4 tA = __ldcs(&t4[base]), tB = __ldcs(&t4[base + 1]);
        float4 wA = __ldcs(&w4[base]), wB = __ldcs(&w4[base + 1]);

        float pp[8] = {pA.x, pA.y, pA.z, pA.w, pB.x, pB.y, pB.z, pB.w};
        float tt[8] = {tA.x, tA.y, tA.z, tA.w, tB.x, tB.y, tB.z, tB.w};
        float ww[8] = {wA.x, wA.y, wA.z, wA.w, wB.x, wB.y, wB.z, wB.w};

        // leaf state over 8 contiguous elements (branch-free); bce into wacc
        int cur = 0, best = 0, pref = 0, all = 1;
#pragma unroll
        for (int e = 0; e < 8; e++) {
            bool tb = (tt[e] > 0.5f);
            bool pb = (pp[e] > 0.5f);
            int corr = (tb == pb) ? 1 : 0;
            float v = tb ? (pp[e] + EPS) : ((1.0f - pp[e]) + EPS);
            wacc = fmaf(ww[e], -__logf(v), wacc);
            cur  = corr ? (cur + 1) : 0;
            best = max(best, cur);
            all &= corr;
            pref += all;
        }
        int suf = cur;

        // warp tree: 8-elem leaves -> 256-elem warp segment (valid in lane 0)
#pragma unroll
        for (int st = 0; st < 5; st++) {
            int len = 8 << st;
            int op = __shfl_down_sync(0xffffffffu, pref, 1 << st);
            int os = __shfl_down_sync(0xffffffffu, suf,  1 << st);
            int ob = __shfl_down_sync(0xffffffffu, best, 1 << st);
            SEG_COMBINE(pref, suf, best, len, op, os, ob, len);
        }

        if (lane == 0) {
            shp[s][warp] = pref; shs[s][warp] = suf; shb[s][warp] = best;
            mbar_arrive(fullb + 8u * s);          // release: seg visible
        }

        if (consumer) {
            mbar_wait(fullb + 8u * s, (unsigned)(c & 1));   // acquire all 16 segs
            if (lane == 0) {
                int ap = shp[s][0], as = shs[s][0], ab = shb[s][0];
#pragma unroll
                for (int wi = 1; wi < 16; wi++)
                    SEG_COMBINE(ap, as, ab, 256 * wi,
                                shp[s][wi], shs[s][wi], shb[s][wi], 256);
                g_ps[row] = ab;                   // released by CTA-end fence
                mbar_arrive(freeb + 8u * s);      // slot reusable
            }
        }
    }

    // ---- CTA end: reduce per-thread bce partials, one fence+atomic per CTA ----
    __syncthreads();   // quiesce pipeline before reusing smem / exiting
#pragma unroll
    for (int s = 16; s > 0; s >>= 1)
        wacc += __shfl_down_sync(0xffffffffu, wacc, s);
    __shared__ float shwf[16];
    if (lane == 0) shwf[warp] = wacc;
    __syncthreads();
    if (tid == 0) {
        float ws = shwf[0];
#pragma unroll
        for (int wi = 1; wi < 16; wi++) ws += shwf[wi];
        g_pw[blockIdx.x] = ws;
        __threadfence();                         // release partials + streaks
        unsigned int done = atomicAdd(&g_count, 1u);
        s_isLast = (done == (unsigned int)(gridDim.x - 1)) ? 1 : 0;
    }
    __syncthreads();

    // ---- last CTA: final deterministic reduction ----
    if (s_isLast) {
        __threadfence();   // acquire: see all CTAs' partials
        double dw = 0.0;
        long long dsi = 0;
        for (int i = tid; i < (int)gridDim.x; i += 512)
            dw += (double)g_pw[i];
        for (int r = tid; r < B; r += 2048) {
            int b0 = g_ps[r], b1 = g_ps[r + 512], b2 = g_ps[r + 1024], b3 = g_ps[r + 1536];
            dsi += (long long)b0 + b1 + b2 + b3;
        }
        __shared__ double    rdw[512];
        __shared__ long long rds[512];
        rdw[tid] = dw;
        rds[tid] = dsi;
        __syncthreads();
#pragma unroll
        for (int st = 256; st > 0; st >>= 1) {
            if (tid < st) { rdw[tid] += rdw[tid + st]; rds[tid] += rds[tid + st]; }
            __syncthreads();
        }
        if (tid == 0) {
            double BN   = (double)B * (double)NCOLS;
            double wbce = rdw[0] / BN;                       // mean(w * bce)
            double cwl  = 1.0 - ((double)rds[0]) / BN;       // mean(1 - streak/N)
            out[0] = (float)(0.5 * wbce + 0.5 * cwl);
            g_count = 0;                                     // reset for next replay
        }
    }
}

extern "C" void kernel_launch(void* const* d_in, const int* in_sizes, int n_in,
                              void* d_out, int out_size)
{
    const float4* p4 = (const float4*)d_in[0];   // y_pred
    const float4* t4 = (const float4*)d_in[1];   // y_true
    const float4* w4 = (const float4*)d_in[2];   // depth_weights
    int total = in_sizes[0];
    int B = total / NCOLS;                       // 8192

    depth_loss_fused_kernel<<<NBLK, 512>>>(p4, t4, w4, (float*)d_out, B);
}